// round 14
// baseline (speedup 1.0000x reference)
#include <cuda_runtime.h>
#include <cuda_bf16.h>
#include <cstdint>

#define H 768
#define SQ 384
#define BB 2
#define NHEADS 12
#define DHEAD 64
#define BS (BB*SQ)   // 768 rows total

// Scratch (allocation-free rule: __device__ globals)
__device__ float g_q[BS*H];
__device__ float g_k[BS*H];
__device__ float g_v[BS*H];
__device__ float g_ctx[BS*H];
// bf16 hi/lo planes (filled by preconv each call)
__device__ __nv_bfloat16 g_xh[BS*H];
__device__ __nv_bfloat16 g_xl[BS*H];
__device__ __nv_bfloat16 g_wh[3*H*H];
__device__ __nv_bfloat16 g_wl[3*H*H];

__device__ __forceinline__ float frcp_approx(float x){ float r; asm("rcp.approx.ftz.f32 %0, %1;" : "=f"(r) : "f"(x)); return r; }
__device__ __forceinline__ float fsqrt_approx(float x){ float r; asm("sqrt.approx.f32 %0, %1;" : "=f"(r) : "f"(x)); return r; }
__device__ __forceinline__ float frsqrt_approx(float x){ float r; asm("rsqrt.approx.f32 %0, %1;" : "=f"(r) : "f"(x)); return r; }

// ---- packed fp32x2 ops ----
union F2U { float2 f; unsigned long long u; };
__device__ __forceinline__ float2 f2fma(float2 a, float2 b, float2 c){
    F2U A, Bv, C, R; A.f = a; Bv.f = b; C.f = c;
    asm("fma.rn.f32x2 %0, %1, %2, %3;" : "=l"(R.u) : "l"(A.u), "l"(Bv.u), "l"(C.u));
    return R.f;
}
__device__ __forceinline__ float2 f2add(float2 a, float2 b){
    F2U A, Bv, R; A.f = a; Bv.f = b;
    asm("add.rn.f32x2 %0, %1, %2;" : "=l"(R.u) : "l"(A.u), "l"(Bv.u));
    return R.f;
}
__device__ __forceinline__ float2 f2mul(float2 a, float2 b){
    F2U A, Bv, R; A.f = a; Bv.f = b;
    asm("mul.rn.f32x2 %0, %1, %2;" : "=l"(R.u) : "l"(A.u), "l"(Bv.u));
    return R.f;
}

// ---- warp-level bf16 MMA + ldmatrix + cp.async ----
__device__ __forceinline__ void mma16816(float* d,
    uint32_t a0, uint32_t a1, uint32_t a2, uint32_t a3,
    uint32_t b0, uint32_t b1)
{
    asm("mma.sync.aligned.m16n8k16.row.col.f32.bf16.bf16.f32 "
        "{%0,%1,%2,%3}, {%4,%5,%6,%7}, {%8,%9}, {%0,%1,%2,%3};"
        : "+f"(d[0]), "+f"(d[1]), "+f"(d[2]), "+f"(d[3])
        : "r"(a0), "r"(a1), "r"(a2), "r"(a3), "r"(b0), "r"(b1));
}
__device__ __forceinline__ void ldmx4(uint32_t* r, uint32_t addr){
    asm volatile("ldmatrix.sync.aligned.m8n8.x4.shared.b16 {%0,%1,%2,%3}, [%4];"
        : "=r"(r[0]), "=r"(r[1]), "=r"(r[2]), "=r"(r[3]) : "r"(addr));
}
__device__ __forceinline__ void ldmx2(uint32_t* r, uint32_t addr){
    asm volatile("ldmatrix.sync.aligned.m8n8.x2.shared.b16 {%0,%1}, [%2];"
        : "=r"(r[0]), "=r"(r[1]) : "r"(addr));
}
__device__ __forceinline__ uint32_t smem_u32(const void* p){
    uint32_t a;
    asm("{ .reg .u64 t; cvta.to.shared.u64 t, %1; cvt.u32.u64 %0, t; }" : "=r"(a) : "l"(p));
    return a;
}
__device__ __forceinline__ void cp16(uint32_t sm, const void* gm){
    asm volatile("cp.async.cg.shared.global [%0], [%1], 16;" :: "r"(sm), "l"(gm));
}
__device__ __forceinline__ void cp_commit(){ asm volatile("cp.async.commit_group;"); }
template<int N> __device__ __forceinline__ void cp_wait(){ asm volatile("cp.async.wait_group %0;" :: "n"(N)); }

// split fp32 -> (hi, lo) bf16 pair, packed as bf16x2 words
__device__ __forceinline__ void split2(float f0, float f1, uint32_t& hw, uint32_t& lw){
    __nv_bfloat16 h0 = __float2bfloat16_rn(f0);
    __nv_bfloat16 h1 = __float2bfloat16_rn(f1);
    __nv_bfloat16 l0 = __float2bfloat16_rn(f0 - __bfloat162float(h0));
    __nv_bfloat16 l1 = __float2bfloat16_rn(f1 - __bfloat162float(h1));
    hw = (uint32_t)*(uint16_t*)&h0 | ((uint32_t)*(uint16_t*)&h1 << 16);
    lw = (uint32_t)*(uint16_t*)&l0 | ((uint32_t)*(uint16_t*)&l1 << 16);
}

// ---------------------------------------------------------------------------
// Kernel 0: convert x / Wq / Wk / Wv to bf16 hi/lo planes.
// grid (576, 4), block 256: each thread converts one float4.
// ---------------------------------------------------------------------------
__global__ __launch_bounds__(256) void preconv(
    const float* __restrict__ x, const float* __restrict__ wq,
    const float* __restrict__ wk, const float* __restrict__ wv)
{
    const int t = blockIdx.y;
    const float* src = (t == 0) ? x : (t == 1) ? wq : (t == 2) ? wk : wv;
    __nv_bfloat16* dh = (t == 0) ? g_xh : g_wh + (size_t)(t-1)*H*H;
    __nv_bfloat16* dl = (t == 0) ? g_xl : g_wl + (size_t)(t-1)*H*H;

    const int idx = (blockIdx.x * 256 + threadIdx.x) * 4;
    float4 v = *(const float4*)&src[idx];
    uint32_t h0, l0, h1, l1;
    split2(v.x, v.y, h0, l0);
    split2(v.z, v.w, h1, l1);
    *(uint2*)((char*)dh + (size_t)idx*2) = make_uint2(h0, h1);
    *(uint2*)((char*)dl + (size_t)idx*2) = make_uint2(l0, l1);
}

// ---------------------------------------------------------------------------
// Kernel 1: fused QKV projection on tensor cores (bf16 2-split, 3 passes).
// CTA 64(M) x 96(N); 256 threads, 8 warps as 2(M) x 4(N) -> warp tile 32x24.
// cp.async 3-deep pipeline from pre-converted bf16 planes; one barrier/slab.
// grid (12, 24) = 288 CTAs -> 2 CTAs/SM.
// Buffer layout: AH@0 (64x80B) | AL@5120 | BH@10240 (96x80B) | BL@17920.
// ---------------------------------------------------------------------------
#define A_BYTES (64*80)            // 5120
#define B_BYTES (96*80)            // 7680
#define BUF_BYTES (2*A_BYTES + 2*B_BYTES)   // 25600
#define QKV_SMEM (3*BUF_BYTES)              // 76800 -> 2 CTAs/SM

__global__ __launch_bounds__(256, 2) void qkv_mma(
    const float* __restrict__ bq, const float* __restrict__ bk,
    const float* __restrict__ bv)
{
    extern __shared__ __nv_bfloat16 smb[];
    const uint32_t sb = smem_u32(smb);

    const int tid = threadIdx.x;
    const int wid = tid >> 5, lane = tid & 31;
    const int warp_m = wid >> 2, warp_n = wid & 3;

    const int m0 = blockIdx.x * 64;
    const int ntile = blockIdx.y;
    const int z = ntile >> 3;
    const int n0 = (ntile & 7) * 96;

    const float* bias = (z == 0) ? bq : (z == 1) ? bk : bv;
    float* out = (z == 0) ? g_q : (z == 1) ? g_k : g_v;

    float acc[2][3][4];
    #pragma unroll
    for (int mi = 0; mi < 2; mi++)
        #pragma unroll
        for (int j = 0; j < 3; j++)
            #pragma unroll
            for (int e = 0; e < 4; e++) acc[mi][j][e] = 0.f;

    // ---- ldmatrix per-lane base addresses ----
    const int lrow = lane & 15;
    const int lkb  = (lane >> 4) * 16;
    const uint32_t aAddrH = sb + (uint32_t)((warp_m*32 + lrow) * 80 + lkb);
    const uint32_t aAddrL = aAddrH + A_BYTES;
    const int jrow  = warp_n*24 + ((lane >> 4) << 3) + (lane & 7);
    const int jkb   = ((lane >> 3) & 1) * 16;
    const uint32_t b4AddrH = sb + 2*A_BYTES + (uint32_t)(jrow * 80 + jkb);
    const uint32_t b4AddrL = b4AddrH + B_BYTES;
    const int jrow2 = warp_n*24 + 16 + (lane & 7);
    const uint32_t b2AddrH = sb + 2*A_BYTES + (uint32_t)(jrow2 * 80 + jkb);
    const uint32_t b2AddrL = b2AddrH + B_BYTES;

    // ---- cp.async seg assignments: 1280 16B-segs, 5 per thread ----
    uint32_t smof[5];
    const __nv_bfloat16* gm[5];
    #pragma unroll
    for (int it = 0; it < 5; it++) {
        int sidx = tid + it * 256;
        if (sidx < 512) {            // A planes
            int a = sidx & 255, r = a >> 2, q = a & 3;
            smof[it] = ((sidx >= 256) ? A_BYTES : 0) + r*80 + q*16;
            gm[it] = ((sidx >= 256) ? g_xl : g_xh) + (size_t)(m0 + r)*H + q*8;
        } else {                     // B planes
            int t2 = sidx - 512;
            int lo = (t2 >= 384);
            int b2 = lo ? t2 - 384 : t2;
            int r = b2 >> 2, q = b2 & 3;
            smof[it] = 2*A_BYTES + (lo ? B_BYTES : 0) + r*80 + q*16;
            gm[it] = (lo ? g_wl : g_wh) + (size_t)z*H*H + (size_t)(n0 + r)*H + q*8;
        }
    }

    // ---- prologue: issue slabs 0 and 1 ----
    #pragma unroll
    for (int it = 0; it < 5; it++) cp16(sb + smof[it], gm[it]);
    cp_commit();
    #pragma unroll
    for (int it = 0; it < 5; it++) cp16(sb + BUF_BYTES + smof[it], (const char*)gm[it] + 64);
    cp_commit();

    uint32_t bufB = 0;        // (s % 3) * BUF_BYTES
    for (int s = 0; s < 24; s++) {
        if (s < 23) cp_wait<1>(); else cp_wait<0>();
        __syncthreads();      // slab s visible; all warps done with MMA(s-1)

        // issue slab s+2 into buffer (s+2)%3 == (s-1)%3 (drained at barrier above)
        if (s < 22) {
            uint32_t nb = bufB + 2*BUF_BYTES;
            if (nb >= 3*BUF_BYTES) nb -= 3*BUF_BYTES;
            const int koff = (s + 2) * 64;   // bytes: 32 bf16 per slab
            #pragma unroll
            for (int it = 0; it < 5; it++) cp16(sb + nb + smof[it], (const char*)gm[it] + koff);
            cp_commit();
        }

        // ---- MMA slab s ----
        #pragma unroll
        for (int ks = 0; ks < 2; ks++) {
            const uint32_t kb = bufB + ks * 32;
            uint32_t Ah[2][4], Al[2][4], B4h[4], B4l[4], B2h[2], B2l[2];
            ldmx4(Ah[0], aAddrH + kb);
            ldmx4(Ah[1], aAddrH + kb + 16*80);
            ldmx4(Al[0], aAddrL + kb);
            ldmx4(Al[1], aAddrL + kb + 16*80);
            ldmx4(B4h, b4AddrH + kb);
            ldmx4(B4l, b4AddrL + kb);
            ldmx2(B2h, b2AddrH + kb);
            ldmx2(B2l, b2AddrL + kb);
            #pragma unroll
            for (int mi = 0; mi < 2; mi++) {
                mma16816(acc[mi][0], Ah[mi][0],Ah[mi][1],Ah[mi][2],Ah[mi][3], B4h[0],B4h[1]);
                mma16816(acc[mi][0], Ah[mi][0],Ah[mi][1],Ah[mi][2],Ah[mi][3], B4l[0],B4l[1]);
                mma16816(acc[mi][0], Al[mi][0],Al[mi][1],Al[mi][2],Al[mi][3], B4h[0],B4h[1]);
                mma16816(acc[mi][1], Ah[mi][0],Ah[mi][1],Ah[mi][2],Ah[mi][3], B4h[2],B4h[3]);
                mma16816(acc[mi][1], Ah[mi][0],Ah[mi][1],Ah[mi][2],Ah[mi][3], B4l[2],B4l[3]);
                mma16816(acc[mi][1], Al[mi][0],Al[mi][1],Al[mi][2],Al[mi][3], B4h[2],B4h[3]);
                mma16816(acc[mi][2], Ah[mi][0],Ah[mi][1],Ah[mi][2],Ah[mi][3], B2h[0],B2h[1]);
                mma16816(acc[mi][2], Ah[mi][0],Ah[mi][1],Ah[mi][2],Ah[mi][3], B2l[0],B2l[1]);
                mma16816(acc[mi][2], Al[mi][0],Al[mi][1],Al[mi][2],Al[mi][3], B2h[0],B2h[1]);
            }
        }
        bufB += BUF_BYTES;
        if (bufB >= 3*BUF_BYTES) bufB = 0;
    }

    // ---- epilogue ----
    const int gid = lane >> 2, tg = lane & 3;
    #pragma unroll
    for (int mi = 0; mi < 2; mi++) {
        int r0 = m0 + warp_m * 32 + mi * 16 + gid;
        #pragma unroll
        for (int j = 0; j < 3; j++) {
            int nc = n0 + warp_n * 24 + j * 8 + tg * 2;
            float b0 = bias[nc], b1 = bias[nc + 1];
            *(float2*)&out[(size_t)r0 * H + nc]       = make_float2(acc[mi][j][0] + b0, acc[mi][j][1] + b1);
            *(float2*)&out[(size_t)(r0 + 8) * H + nc] = make_float2(acc[mi][j][2] + b0, acc[mi][j][3] + b1);
        }
    }
}

// ---------------------------------------------------------------------------
// Kernel 2: attention with p=-2 distance scores.
// I-tile 32 rows -> grid (12, 12, 2) = 288 CTAs, block 512, smem 92.9KB
// -> 2 CTAs/SM. Double-buffered K/V tiles; 4-way reciprocal pairing;
// Q,K scaled x4, compensated by score = -0.5 * acc^(-1/4).
// ---------------------------------------------------------------------------
#define ITILE 32
#define QSTR 68
#define KSTR 68
#define SCW 385
#define ATTN_SMEM ((ITILE*QSTR + 2*64*QSTR + ITILE*SCW + ITILE)*4)   // 92928 B

__global__ __launch_bounds__(512, 2) void attn_kernel()
{
    extern __shared__ float sm[];
    float* qs  = sm;                         // [32][QSTR]
    float* kv0 = sm + ITILE*QSTR;            // [64][QSTR]
    float* kv1 = kv0 + 64*QSTR;              // [64][QSTR]
    float* sc  = kv1 + 64*QSTR;              // [32][SCW]
    float* rowsum = sc + ITILE*SCW;          // [32]

    const int tid = threadIdx.x;
    const int b = blockIdx.z, h = blockIdx.y;
    const int i0 = blockIdx.x * ITILE;

    const float* Qb = g_q + (size_t)(b*SQ)*H + h*DHEAD;
    const float* Kb = g_k + (size_t)(b*SQ)*H + h*DHEAD;
    const float* Vb = g_v + (size_t)(b*SQ)*H + h*DHEAD;

    // Q tile [32][64], scaled by 4: 512 float4 segs, 1/thread
    {
        int i = tid >> 4, c4 = (tid & 15) << 2;
        float4 v = *(const float4*)&Qb[(size_t)(i0+i)*H + c4];
        v.x *= 4.f; v.y *= 4.f; v.z *= 4.f; v.w *= 4.f;
        *(float4*)&qs[i*QSTR + c4] = v;
    }

    const int tx = tid & 31;   // j group: 2 cols each (64 j)
    const int ty = tid >> 5;   // i group: 2 rows each (32 i)

    // per-thread K/V tile-load coords (2 segs)
    const int kr0 = tid >> 4, kc0 = (tid & 15) << 2;
    const int kr1 = kr0 + 32;

    // ---- Phase 1: scores, double-buffered K tiles ----
    float4 pk0 = *(const float4*)&Kb[(size_t)(kr0)*H + kc0];
    float4 pk1 = *(const float4*)&Kb[(size_t)(kr1)*H + kc0];

    for (int jt = 0; jt < 6; jt++) {
        int j0 = jt * 64;
        float* kb = (jt & 1) ? kv1 : kv0;
        kb[(kc0+0)*KSTR + kr0] = -4.f*pk0.x;
        kb[(kc0+1)*KSTR + kr0] = -4.f*pk0.y;
        kb[(kc0+2)*KSTR + kr0] = -4.f*pk0.z;
        kb[(kc0+3)*KSTR + kr0] = -4.f*pk0.w;
        kb[(kc0+0)*KSTR + kr1] = -4.f*pk1.x;
        kb[(kc0+1)*KSTR + kr1] = -4.f*pk1.y;
        kb[(kc0+2)*KSTR + kr1] = -4.f*pk1.z;
        kb[(kc0+3)*KSTR + kr1] = -4.f*pk1.w;
        __syncthreads();
        if (jt < 5) {
            pk0 = *(const float4*)&Kb[(size_t)(j0 + 64 + kr0)*H + kc0];
            pk1 = *(const float4*)&Kb[(size_t)(j0 + 64 + kr1)*H + kc0];
        }

        float2 acc[2];
        acc[0] = make_float2(0.f, 0.f);
        acc[1] = make_float2(0.f, 0.f);

        #pragma unroll 4
        for (int d = 0; d < 64; d += 4) {
            float2 nk0 = *(const float2*)&kb[(d+0)*KSTR + tx*2];
            float2 nk1 = *(const float2*)&kb[(d+1)*KSTR + tx*2];
            float2 nk2 = *(const float2*)&kb[(d+2)*KSTR + tx*2];
            float2 nk3 = *(const float2*)&kb[(d+3)*KSTR + tx*2];
            #pragma unroll
            for (int i = 0; i < 2; i++) {
                float4 q = *(const float4*)&qs[(ty*2+i)*QSTR + d];
                float2 d0 = f2add(make_float2(q.x, q.x), nk0);
                float2 d1 = f2add(make_float2(q.y, q.y), nk1);
                float2 d2 = f2add(make_float2(q.z, q.z), nk2);
                float2 d3 = f2add(make_float2(q.w, q.w), nk3);
                float2 a  = f2mul(d0, d0);
                float2 bq2 = f2mul(d1, d1);
                float2 c  = f2mul(d2, d2);
                float2 e  = f2mul(d3, d3);
                float2 ab = f2mul(a, bq2);
                float2 ce = f2mul(c, e);
                float2 sab = f2add(a, bq2);
                float2 sce = f2add(c, e);
                float2 num = f2fma(sab, ce, f2mul(sce, ab));
                float2 den = f2mul(ab, ce);
                float2 r   = make_float2(frcp_approx(den.x), frcp_approx(den.y));
                acc[i] = f2fma(num, r, acc[i]);
            }
        }
        #pragma unroll
        for (int i = 0; i < 2; i++) {
            float* row = &sc[(ty*2+i)*SCW + j0 + tx*2];
            row[0] = -0.5f * frsqrt_approx(fsqrt_approx(acc[i].x));
            row[1] = -0.5f * frsqrt_approx(fsqrt_approx(acc[i].y));
        }
    }
    __syncthreads();

    // prefetch V tile 0 (hides LDG under softmax)
    float4 pv0 = *(const float4*)&Vb[(size_t)(kr0)*H + kc0];
    float4 pv1 = *(const float4*)&Vb[(size_t)(kr1)*H + kc0];

    // ---- Phase 2: softmax rows (32 rows, 16 warps -> 2 rows each) ----
    {
        const int wid = tid >> 5, lane = tid & 31;
        for (int i = wid; i < ITILE; i += 16) {
            float m = -3.402823466e38f;
            for (int j = lane; j < SQ; j += 32) m = fmaxf(m, sc[i*SCW + j]);
            #pragma unroll
            for (int o = 16; o; o >>= 1) m = fmaxf(m, __shfl_xor_sync(0xffffffffu, m, o));
            float s = 0.f;
            for (int j = lane; j < SQ; j += 32) {
                float p = __expf(sc[i*SCW + j] - m);
                sc[i*SCW + j] = p;
                s += p;
            }
            #pragma unroll
            for (int o = 16; o; o >>= 1) s += __shfl_xor_sync(0xffffffffu, s, o);
            if (lane == 0) rowsum[i] = s;
        }
    }
    __syncthreads();

    // ---- Phase 3: ctx = P @ V, double-buffered V tiles ----
    float2 acc2[2];
    acc2[0] = make_float2(0.f, 0.f);
    acc2[1] = make_float2(0.f, 0.f);

    for (int jt = 0; jt < 6; jt++) {
        int j0 = jt * 64;
        float* vb = (jt & 1) ? kv1 : kv0;
        *(float4*)&vb[kr0*QSTR + kc0] = pv0;
        *(float4*)&vb[kr1*QSTR + kc0] = pv1;
        __syncthreads();
        if (jt < 5) {
            pv0 = *(const float4*)&Vb[(size_t)(j0 + 64 + kr0)*H + kc0];
            pv1 = *(const float4*)&Vb[(size_t)(j0 + 64 + kr1)*H + kc0];
        }
        #pragma unroll 4
        for (int j = 0; j < 64; j++) {
            float2 vv = *(const float2*)&vb[j*QSTR + tx*2];
            #pragma unroll
            for (int i = 0; i < 2; i++) {
                float pvs = sc[(ty*2+i)*SCW + j0 + j];
                acc2[i] = f2fma(make_float2(pvs, pvs), vv, acc2[i]);
            }
        }
    }

    #pragma unroll
    for (int i = 0; i < 2; i++) {
        float rs = frcp_approx(rowsum[ty*2 + i]);
        int row = i0 + ty*2 + i;
        float* op = &g_ctx[(size_t)(b*SQ + row)*H + h*DHEAD + tx*2];
        op[0] = acc2[i].x * rs;
        op[1] = acc2[i].y * rs;
    }
}

// ---------------------------------------------------------------------------
// Kernel 3: residual + LayerNorm.
// ---------------------------------------------------------------------------
__global__ __launch_bounds__(256) void ln_kernel(
    const float* __restrict__ x, const float* __restrict__ gam,
    const float* __restrict__ bet, float* __restrict__ out)
{
    const int r = blockIdx.x;
    const float* xr = x + (size_t)r * H;
    const float* cr = g_ctx + (size_t)r * H;
    const int tid = threadIdx.x;

    __shared__ float redS[8], redQ[8];

    float y[3];
    float s = 0.f, ss = 0.f;
    #pragma unroll
    for (int k = 0; k < 3; k++) {
        int j = tid + k * 256;
        y[k] = xr[j] + cr[j];
        s += y[k];
        ss += y[k] * y[k];
    }
    #pragma unroll
    for (int o = 16; o; o >>= 1) {
        s  += __shfl_xor_sync(0xffffffffu, s, o);
        ss += __shfl_xor_sync(0xffffffffu, ss, o);
    }
    const int wid = tid >> 5, lane = tid & 31;
    if (lane == 0) { redS[wid] = s; redQ[wid] = ss; }
    __syncthreads();
    if (tid == 0) {
        float a = 0.f, b2 = 0.f;
        #pragma unroll
        for (int w = 0; w < 8; w++) { a += redS[w]; b2 += redQ[w]; }
        redS[0] = a; redQ[0] = b2;
    }
    __syncthreads();
    const float mu  = redS[0] * (1.f / (float)H);
    const float var = redQ[0] * (1.f / (float)H) - mu * mu;
    const float inv = rsqrtf(var + 1e-12f);

    #pragma unroll
    for (int k = 0; k < 3; k++) {
        int j = tid + k * 256;
        out[(size_t)r * H + j] = (y[k] - mu) * inv * gam[j] + bet[j];
    }
}

// ---------------------------------------------------------------------------
extern "C" void kernel_launch(void* const* d_in, const int* in_sizes, int n_in,
                              void* d_out, int out_size)
{
    const float* x   = (const float*)d_in[0];
    const float* Wq  = (const float*)d_in[1];
    const float* bq  = (const float*)d_in[2];
    const float* Wk  = (const float*)d_in[3];
    const float* bk  = (const float*)d_in[4];
    const float* Wv  = (const float*)d_in[5];
    const float* bv  = (const float*)d_in[6];
    const float* lng = (const float*)d_in[7];
    const float* lnb = (const float*)d_in[8];
    float* out = (float*)d_out;

    // 0) convert x, Wq, Wk, Wv to bf16 hi/lo planes
    preconv<<<dim3(576, 4), 256>>>(x, Wq, Wk, Wv);

    // 1) fused QKV projection on tensor cores: grid (12, 24) = 288 CTAs, 2/SM
    cudaFuncSetAttribute(qkv_mma, cudaFuncAttributeMaxDynamicSharedMemorySize, QKV_SMEM);
    qkv_mma<<<dim3(12, 24), 256, QKV_SMEM>>>(bq, bk, bv);

    // 2) attention: grid (12, 12, 2) = 288 CTAs, 2/SM
    cudaFuncSetAttribute(attn_kernel, cudaFuncAttributeMaxDynamicSharedMemorySize, ATTN_SMEM);
    attn_kernel<<<dim3(12, NHEADS, BB), 512, ATTN_SMEM>>>();

    // 3) residual + LayerNorm
    ln_kernel<<<BS, 256>>>(x, lng, lnb, out);
}

// round 15
// speedup vs baseline: 1.0637x; 1.0637x over previous
#include <cuda_runtime.h>
#include <cuda_bf16.h>
#include <cstdint>

#define H 768
#define SQ 384
#define BB 2
#define NHEADS 12
#define DHEAD 64
#define BS (BB*SQ)   // 768 rows total

// Scratch (allocation-free rule: __device__ globals)
__device__ float g_q[BS*H];
__device__ float g_k[BS*H];
__device__ float g_v[BS*H];
__device__ float g_ctx[BS*H];
// bf16 hi/lo planes (filled by preconv each call)
__device__ __nv_bfloat16 g_xh[BS*H];
__device__ __nv_bfloat16 g_xl[BS*H];
__device__ __nv_bfloat16 g_wh[3*H*H];
__device__ __nv_bfloat16 g_wl[3*H*H];

__device__ __forceinline__ float frcp_approx(float x){ float r; asm("rcp.approx.ftz.f32 %0, %1;" : "=f"(r) : "f"(x)); return r; }
__device__ __forceinline__ float fsqrt_approx(float x){ float r; asm("sqrt.approx.f32 %0, %1;" : "=f"(r) : "f"(x)); return r; }
__device__ __forceinline__ float frsqrt_approx(float x){ float r; asm("rsqrt.approx.f32 %0, %1;" : "=f"(r) : "f"(x)); return r; }

// ---- packed fp32x2 ops ----
union F2U { float2 f; unsigned long long u; };
__device__ __forceinline__ float2 f2fma(float2 a, float2 b, float2 c){
    F2U A, Bv, C, R; A.f = a; Bv.f = b; C.f = c;
    asm("fma.rn.f32x2 %0, %1, %2, %3;" : "=l"(R.u) : "l"(A.u), "l"(Bv.u), "l"(C.u));
    return R.f;
}
__device__ __forceinline__ float2 f2add(float2 a, float2 b){
    F2U A, Bv, R; A.f = a; Bv.f = b;
    asm("add.rn.f32x2 %0, %1, %2;" : "=l"(R.u) : "l"(A.u), "l"(Bv.u));
    return R.f;
}
__device__ __forceinline__ float2 f2mul(float2 a, float2 b){
    F2U A, Bv, R; A.f = a; Bv.f = b;
    asm("mul.rn.f32x2 %0, %1, %2;" : "=l"(R.u) : "l"(A.u), "l"(Bv.u));
    return R.f;
}

// ---- warp-level bf16 MMA + ldmatrix + cp.async ----
__device__ __forceinline__ void mma16816(float* d,
    uint32_t a0, uint32_t a1, uint32_t a2, uint32_t a3,
    uint32_t b0, uint32_t b1)
{
    asm("mma.sync.aligned.m16n8k16.row.col.f32.bf16.bf16.f32 "
        "{%0,%1,%2,%3}, {%4,%5,%6,%7}, {%8,%9}, {%0,%1,%2,%3};"
        : "+f"(d[0]), "+f"(d[1]), "+f"(d[2]), "+f"(d[3])
        : "r"(a0), "r"(a1), "r"(a2), "r"(a3), "r"(b0), "r"(b1));
}
__device__ __forceinline__ void ldmx4(uint32_t* r, uint32_t addr){
    asm volatile("ldmatrix.sync.aligned.m8n8.x4.shared.b16 {%0,%1,%2,%3}, [%4];"
        : "=r"(r[0]), "=r"(r[1]), "=r"(r[2]), "=r"(r[3]) : "r"(addr));
}
__device__ __forceinline__ void ldmx2(uint32_t* r, uint32_t addr){
    asm volatile("ldmatrix.sync.aligned.m8n8.x2.shared.b16 {%0,%1}, [%2];"
        : "=r"(r[0]), "=r"(r[1]) : "r"(addr));
}
__device__ __forceinline__ uint32_t smem_u32(const void* p){
    uint32_t a;
    asm("{ .reg .u64 t; cvta.to.shared.u64 t, %1; cvt.u32.u64 %0, t; }" : "=r"(a) : "l"(p));
    return a;
}
__device__ __forceinline__ void cp16(uint32_t sm, const void* gm){
    asm volatile("cp.async.cg.shared.global [%0], [%1], 16;" :: "r"(sm), "l"(gm));
}
__device__ __forceinline__ void cp_commit(){ asm volatile("cp.async.commit_group;"); }
template<int N> __device__ __forceinline__ void cp_wait(){ asm volatile("cp.async.wait_group %0;" :: "n"(N)); }

// split fp32 -> (hi, lo) bf16 pair, packed as bf16x2 words
__device__ __forceinline__ void split2(float f0, float f1, uint32_t& hw, uint32_t& lw){
    __nv_bfloat16 h0 = __float2bfloat16_rn(f0);
    __nv_bfloat16 h1 = __float2bfloat16_rn(f1);
    __nv_bfloat16 l0 = __float2bfloat16_rn(f0 - __bfloat162float(h0));
    __nv_bfloat16 l1 = __float2bfloat16_rn(f1 - __bfloat162float(h1));
    hw = (uint32_t)*(uint16_t*)&h0 | ((uint32_t)*(uint16_t*)&h1 << 16);
    lw = (uint32_t)*(uint16_t*)&l0 | ((uint32_t)*(uint16_t*)&l1 << 16);
}

// ---------------------------------------------------------------------------
// Kernel 0: convert x / Wq / Wk / Wv to bf16 hi/lo planes.
// grid (576, 4), block 256: each thread converts one float4.
// ---------------------------------------------------------------------------
__global__ __launch_bounds__(256) void preconv(
    const float* __restrict__ x, const float* __restrict__ wq,
    const float* __restrict__ wk, const float* __restrict__ wv)
{
    const int t = blockIdx.y;
    const float* src = (t == 0) ? x : (t == 1) ? wq : (t == 2) ? wk : wv;
    __nv_bfloat16* dh = (t == 0) ? g_xh : g_wh + (size_t)(t-1)*H*H;
    __nv_bfloat16* dl = (t == 0) ? g_xl : g_wl + (size_t)(t-1)*H*H;

    const int idx = (blockIdx.x * 256 + threadIdx.x) * 4;
    float4 v = *(const float4*)&src[idx];
    uint32_t h0, l0, h1, l1;
    split2(v.x, v.y, h0, l0);
    split2(v.z, v.w, h1, l1);
    *(uint2*)((char*)dh + (size_t)idx*2) = make_uint2(h0, h1);
    *(uint2*)((char*)dl + (size_t)idx*2) = make_uint2(l0, l1);
}

// ---------------------------------------------------------------------------
// Kernel 1: fused QKV projection on tensor cores (bf16 2-split, 3 passes).
// CTA 64(M) x 96(N); 256 threads, 8 warps as 2(M) x 4(N) -> warp tile 32x24.
// cp.async 3-deep pipeline from pre-converted bf16 planes; one barrier/slab.
// grid (12, 24) = 288 CTAs -> 2 CTAs/SM.
// Buffer layout: AH@0 (64x80B) | AL@5120 | BH@10240 (96x80B) | BL@17920.
// ---------------------------------------------------------------------------
#define A_BYTES (64*80)            // 5120
#define B_BYTES (96*80)            // 7680
#define BUF_BYTES (2*A_BYTES + 2*B_BYTES)   // 25600
#define QKV_SMEM (3*BUF_BYTES)              // 76800 -> 2 CTAs/SM

__global__ __launch_bounds__(256, 2) void qkv_mma(
    const float* __restrict__ bq, const float* __restrict__ bk,
    const float* __restrict__ bv)
{
    extern __shared__ __nv_bfloat16 smb[];
    const uint32_t sb = smem_u32(smb);

    const int tid = threadIdx.x;
    const int wid = tid >> 5, lane = tid & 31;
    const int warp_m = wid >> 2, warp_n = wid & 3;

    const int m0 = blockIdx.x * 64;
    const int ntile = blockIdx.y;
    const int z = ntile >> 3;
    const int n0 = (ntile & 7) * 96;

    const float* bias = (z == 0) ? bq : (z == 1) ? bk : bv;
    float* out = (z == 0) ? g_q : (z == 1) ? g_k : g_v;

    float acc[2][3][4];
    #pragma unroll
    for (int mi = 0; mi < 2; mi++)
        #pragma unroll
        for (int j = 0; j < 3; j++)
            #pragma unroll
            for (int e = 0; e < 4; e++) acc[mi][j][e] = 0.f;

    // ---- ldmatrix per-lane base addresses ----
    const int lrow = lane & 15;
    const int lkb  = (lane >> 4) * 16;
    const uint32_t aAddrH = sb + (uint32_t)((warp_m*32 + lrow) * 80 + lkb);
    const uint32_t aAddrL = aAddrH + A_BYTES;
    const int jrow  = warp_n*24 + ((lane >> 4) << 3) + (lane & 7);
    const int jkb   = ((lane >> 3) & 1) * 16;
    const uint32_t b4AddrH = sb + 2*A_BYTES + (uint32_t)(jrow * 80 + jkb);
    const uint32_t b4AddrL = b4AddrH + B_BYTES;
    const int jrow2 = warp_n*24 + 16 + (lane & 7);
    const uint32_t b2AddrH = sb + 2*A_BYTES + (uint32_t)(jrow2 * 80 + jkb);
    const uint32_t b2AddrL = b2AddrH + B_BYTES;

    // ---- cp.async seg assignments: 1280 16B-segs, 5 per thread ----
    uint32_t smof[5];
    const __nv_bfloat16* gm[5];
    #pragma unroll
    for (int it = 0; it < 5; it++) {
        int sidx = tid + it * 256;
        if (sidx < 512) {            // A planes
            int a = sidx & 255, r = a >> 2, q = a & 3;
            smof[it] = ((sidx >= 256) ? A_BYTES : 0) + r*80 + q*16;
            gm[it] = ((sidx >= 256) ? g_xl : g_xh) + (size_t)(m0 + r)*H + q*8;
        } else {                     // B planes
            int t2 = sidx - 512;
            int lo = (t2 >= 384);
            int b2 = lo ? t2 - 384 : t2;
            int r = b2 >> 2, q = b2 & 3;
            smof[it] = 2*A_BYTES + (lo ? B_BYTES : 0) + r*80 + q*16;
            gm[it] = (lo ? g_wl : g_wh) + (size_t)z*H*H + (size_t)(n0 + r)*H + q*8;
        }
    }

    // ---- prologue: issue slabs 0 and 1 ----
    #pragma unroll
    for (int it = 0; it < 5; it++) cp16(sb + smof[it], gm[it]);
    cp_commit();
    #pragma unroll
    for (int it = 0; it < 5; it++) cp16(sb + BUF_BYTES + smof[it], (const char*)gm[it] + 64);
    cp_commit();

    uint32_t bufB = 0;        // (s % 3) * BUF_BYTES
    for (int s = 0; s < 24; s++) {
        if (s < 23) cp_wait<1>(); else cp_wait<0>();
        __syncthreads();      // slab s visible; all warps done with MMA(s-1)

        // issue slab s+2 into buffer (s+2)%3 == (s-1)%3 (drained at barrier above)
        if (s < 22) {
            uint32_t nb = bufB + 2*BUF_BYTES;
            if (nb >= 3*BUF_BYTES) nb -= 3*BUF_BYTES;
            const int koff = (s + 2) * 64;   // bytes: 32 bf16 per slab
            #pragma unroll
            for (int it = 0; it < 5; it++) cp16(sb + nb + smof[it], (const char*)gm[it] + koff);
            cp_commit();
        }

        // ---- MMA slab s ----
        #pragma unroll
        for (int ks = 0; ks < 2; ks++) {
            const uint32_t kb = bufB + ks * 32;
            uint32_t Ah[2][4], Al[2][4], B4h[4], B4l[4], B2h[2], B2l[2];
            ldmx4(Ah[0], aAddrH + kb);
            ldmx4(Ah[1], aAddrH + kb + 16*80);
            ldmx4(Al[0], aAddrL + kb);
            ldmx4(Al[1], aAddrL + kb + 16*80);
            ldmx4(B4h, b4AddrH + kb);
            ldmx4(B4l, b4AddrL + kb);
            ldmx2(B2h, b2AddrH + kb);
            ldmx2(B2l, b2AddrL + kb);
            #pragma unroll
            for (int mi = 0; mi < 2; mi++) {
                mma16816(acc[mi][0], Ah[mi][0],Ah[mi][1],Ah[mi][2],Ah[mi][3], B4h[0],B4h[1]);
                mma16816(acc[mi][0], Ah[mi][0],Ah[mi][1],Ah[mi][2],Ah[mi][3], B4l[0],B4l[1]);
                mma16816(acc[mi][0], Al[mi][0],Al[mi][1],Al[mi][2],Al[mi][3], B4h[0],B4h[1]);
                mma16816(acc[mi][1], Ah[mi][0],Ah[mi][1],Ah[mi][2],Ah[mi][3], B4h[2],B4h[3]);
                mma16816(acc[mi][1], Ah[mi][0],Ah[mi][1],Ah[mi][2],Ah[mi][3], B4l[2],B4l[3]);
                mma16816(acc[mi][1], Al[mi][0],Al[mi][1],Al[mi][2],Al[mi][3], B4h[2],B4h[3]);
                mma16816(acc[mi][2], Ah[mi][0],Ah[mi][1],Ah[mi][2],Ah[mi][3], B2h[0],B2h[1]);
                mma16816(acc[mi][2], Ah[mi][0],Ah[mi][1],Ah[mi][2],Ah[mi][3], B2l[0],B2l[1]);
                mma16816(acc[mi][2], Al[mi][0],Al[mi][1],Al[mi][2],Al[mi][3], B2h[0],B2h[1]);
            }
        }
        bufB += BUF_BYTES;
        if (bufB >= 3*BUF_BYTES) bufB = 0;
    }

    // ---- epilogue ----
    const int gid = lane >> 2, tg = lane & 3;
    #pragma unroll
    for (int mi = 0; mi < 2; mi++) {
        int r0 = m0 + warp_m * 32 + mi * 16 + gid;
        #pragma unroll
        for (int j = 0; j < 3; j++) {
            int nc = n0 + warp_n * 24 + j * 8 + tg * 2;
            float b0 = bias[nc], b1 = bias[nc + 1];
            *(float2*)&out[(size_t)r0 * H + nc]       = make_float2(acc[mi][j][0] + b0, acc[mi][j][1] + b1);
            *(float2*)&out[(size_t)(r0 + 8) * H + nc] = make_float2(acc[mi][j][2] + b0, acc[mi][j][3] + b1);
        }
    }
}

// ---------------------------------------------------------------------------
// Kernel 2: attention with p=-2 distance scores (round-11 best: ITILE=64).
// grid (6, 12, 2), block 512. Double-buffered K/V tiles (reg prefetch, one
// sync per tile). 4-way reciprocal pairing; Q,K scaled x4, compensated by
// score = -0.5 * acc^(-1/4).
// ---------------------------------------------------------------------------
#define QSTR 68
#define KSTR 68
#define SCW 385
#define ATTN_SMEM ((3*64*QSTR + 64*SCW + 64)*4)   // 151040 B

__global__ __launch_bounds__(512) void attn_kernel()
{
    extern __shared__ float sm[];
    float* qs  = sm;                       // [64][QSTR]
    float* kv0 = sm + 64*QSTR;             // tile buffer 0
    float* kv1 = kv0 + 64*QSTR;            // tile buffer 1
    float* sc  = kv1 + 64*QSTR;            // [64][SCW]
    float* rowsum = sc + 64*SCW;

    const int tid = threadIdx.x;
    const int b = blockIdx.z, h = blockIdx.y;
    const int i0 = blockIdx.x * 64;

    const float* Qb = g_q + (size_t)(b*SQ)*H + h*DHEAD;
    const float* Kb = g_k + (size_t)(b*SQ)*H + h*DHEAD;
    const float* Vb = g_v + (size_t)(b*SQ)*H + h*DHEAD;

    // Q tile [64][64], scaled by 4
    for (int idx = tid; idx < 64*16; idx += 512) {
        int i = idx >> 4, c4 = (idx & 15) << 2;
        float4 v = *(const float4*)&Qb[(size_t)(i0+i)*H + c4];
        v.x *= 4.f; v.y *= 4.f; v.z *= 4.f; v.w *= 4.f;
        *(float4*)&qs[i*QSTR + c4] = v;
    }

    const int tx = tid & 31;   // j group: 2 cols each (64 j)
    const int ty = tid >> 5;   // i group: 4 rows each (64 i)

    // per-thread tile-load coords (2 segs: tid, tid+512)
    const int kr0 = tid >> 4, kc0 = (tid & 15) << 2;
    const int kr1 = kr0 + 32;

    // ---- Phase 1: scores, double-buffered K tiles ----
    float4 pk0 = *(const float4*)&Kb[(size_t)(kr0)*H + kc0];
    float4 pk1 = *(const float4*)&Kb[(size_t)(kr1)*H + kc0];

    for (int jt = 0; jt < 6; jt++) {
        int j0 = jt * 64;
        float* kb = (jt & 1) ? kv1 : kv0;
        // STS transposed, negated, scaled
        kb[(kc0+0)*KSTR + kr0] = -4.f*pk0.x;
        kb[(kc0+1)*KSTR + kr0] = -4.f*pk0.y;
        kb[(kc0+2)*KSTR + kr0] = -4.f*pk0.z;
        kb[(kc0+3)*KSTR + kr0] = -4.f*pk0.w;
        kb[(kc0+0)*KSTR + kr1] = -4.f*pk1.x;
        kb[(kc0+1)*KSTR + kr1] = -4.f*pk1.y;
        kb[(kc0+2)*KSTR + kr1] = -4.f*pk1.z;
        kb[(kc0+3)*KSTR + kr1] = -4.f*pk1.w;
        __syncthreads();
        if (jt < 5) {
            pk0 = *(const float4*)&Kb[(size_t)(j0 + 64 + kr0)*H + kc0];
            pk1 = *(const float4*)&Kb[(size_t)(j0 + 64 + kr1)*H + kc0];
        }

        float2 acc[4];
        #pragma unroll
        for (int i = 0; i < 4; i++) acc[i] = make_float2(0.f, 0.f);

        #pragma unroll 4
        for (int d = 0; d < 64; d += 4) {
            float2 nk0 = *(const float2*)&kb[(d+0)*KSTR + tx*2];
            float2 nk1 = *(const float2*)&kb[(d+1)*KSTR + tx*2];
            float2 nk2 = *(const float2*)&kb[(d+2)*KSTR + tx*2];
            float2 nk3 = *(const float2*)&kb[(d+3)*KSTR + tx*2];
            #pragma unroll
            for (int i = 0; i < 4; i++) {
                float4 q = *(const float4*)&qs[(ty*4+i)*QSTR + d];
                float2 d0 = f2add(make_float2(q.x, q.x), nk0);
                float2 d1 = f2add(make_float2(q.y, q.y), nk1);
                float2 d2 = f2add(make_float2(q.z, q.z), nk2);
                float2 d3 = f2add(make_float2(q.w, q.w), nk3);
                float2 a  = f2mul(d0, d0);
                float2 bq2 = f2mul(d1, d1);
                float2 c  = f2mul(d2, d2);
                float2 e  = f2mul(d3, d3);
                float2 ab = f2mul(a, bq2);
                float2 ce = f2mul(c, e);
                float2 sab = f2add(a, bq2);
                float2 sce = f2add(c, e);
                float2 num = f2fma(sab, ce, f2mul(sce, ab));
                float2 den = f2mul(ab, ce);
                float2 r   = make_float2(frcp_approx(den.x), frcp_approx(den.y));
                acc[i] = f2fma(num, r, acc[i]);
            }
        }
        #pragma unroll
        for (int i = 0; i < 4; i++) {
            float* row = &sc[(ty*4+i)*SCW + j0 + tx*2];
            row[0] = -0.5f * frsqrt_approx(fsqrt_approx(acc[i].x));
            row[1] = -0.5f * frsqrt_approx(fsqrt_approx(acc[i].y));
        }
    }
    __syncthreads();

    // prefetch V tile 0 (hides LDG under softmax)
    float4 pv0 = *(const float4*)&Vb[(size_t)(kr0)*H + kc0];
    float4 pv1 = *(const float4*)&Vb[(size_t)(kr1)*H + kc0];

    // ---- Phase 2: softmax rows ----
    {
        const int wid = tid >> 5, lane = tid & 31;
        for (int i = wid; i < 64; i += 16) {
            float m = -3.402823466e38f;
            for (int j = lane; j < SQ; j += 32) m = fmaxf(m, sc[i*SCW + j]);
            #pragma unroll
            for (int o = 16; o; o >>= 1) m = fmaxf(m, __shfl_xor_sync(0xffffffffu, m, o));
            float s = 0.f;
            for (int j = lane; j < SQ; j += 32) {
                float p = __expf(sc[i*SCW + j] - m);
                sc[i*SCW + j] = p;
                s += p;
            }
            #pragma unroll
            for (int o = 16; o; o >>= 1) s += __shfl_xor_sync(0xffffffffu, s, o);
            if (lane == 0) rowsum[i] = s;
        }
    }
    __syncthreads();

    // ---- Phase 3: ctx = P @ V, double-buffered V tiles ----
    float2 acc2[4];
    #pragma unroll
    for (int i = 0; i < 4; i++) acc2[i] = make_float2(0.f, 0.f);

    for (int jt = 0; jt < 6; jt++) {
        int j0 = jt * 64;
        float* vb = (jt & 1) ? kv1 : kv0;
        *(float4*)&vb[kr0*QSTR + kc0] = pv0;
        *(float4*)&vb[kr1*QSTR + kc0] = pv1;
        __syncthreads();
        if (jt < 5) {
            pv0 = *(const float4*)&Vb[(size_t)(j0 + 64 + kr0)*H + kc0];
            pv1 = *(const float4*)&Vb[(size_t)(j0 + 64 + kr1)*H + kc0];
        }
        #pragma unroll 4
        for (int j = 0; j < 64; j++) {
            float2 vv = *(const float2*)&vb[j*QSTR + tx*2];
            #pragma unroll
            for (int i = 0; i < 4; i++) {
                float pvs = sc[(ty*4+i)*SCW + j0 + j];
                acc2[i] = f2fma(make_float2(pvs, pvs), vv, acc2[i]);
            }
        }
    }

    #pragma unroll
    for (int i = 0; i < 4; i++) {
        float rs = frcp_approx(rowsum[ty*4 + i]);
        int row = i0 + ty*4 + i;
        float* op = &g_ctx[(size_t)(b*SQ + row)*H + h*DHEAD + tx*2];
        op[0] = acc2[i].x * rs;
        op[1] = acc2[i].y * rs;
    }
}

// ---------------------------------------------------------------------------
// Kernel 3: residual + LayerNorm.
// ---------------------------------------------------------------------------
__global__ __launch_bounds__(256) void ln_kernel(
    const float* __restrict__ x, const float* __restrict__ gam,
    const float* __restrict__ bet, float* __restrict__ out)
{
    const int r = blockIdx.x;
    const float* xr = x + (size_t)r * H;
    const float* cr = g_ctx + (size_t)r * H;
    const int tid = threadIdx.x;

    __shared__ float redS[8], redQ[8];

    float y[3];
    float s = 0.f, ss = 0.f;
    #pragma unroll
    for (int k = 0; k < 3; k++) {
        int j = tid + k * 256;
        y[k] = xr[j] + cr[j];
        s += y[k];
        ss += y[k] * y[k];
    }
    #pragma unroll
    for (int o = 16; o; o >>= 1) {
        s  += __shfl_xor_sync(0xffffffffu, s, o);
        ss += __shfl_xor_sync(0xffffffffu, ss, o);
    }
    const int wid = tid >> 5, lane = tid & 31;
    if (lane == 0) { redS[wid] = s; redQ[wid] = ss; }
    __syncthreads();
    if (tid == 0) {
        float a = 0.f, b2 = 0.f;
        #pragma unroll
        for (int w = 0; w < 8; w++) { a += redS[w]; b2 += redQ[w]; }
        redS[0] = a; redQ[0] = b2;
    }
    __syncthreads();
    const float mu  = redS[0] * (1.f / (float)H);
    const float var = redQ[0] * (1.f / (float)H) - mu * mu;
    const float inv = rsqrtf(var + 1e-12f);

    #pragma unroll
    for (int k = 0; k < 3; k++) {
        int j = tid + k * 256;
        out[(size_t)r * H + j] = (y[k] - mu) * inv * gam[j] + bet[j];
    }
}

// ---------------------------------------------------------------------------
extern "C" void kernel_launch(void* const* d_in, const int* in_sizes, int n_in,
                              void* d_out, int out_size)
{
    const float* x   = (const float*)d_in[0];
    const float* Wq  = (const float*)d_in[1];
    const float* bq  = (const float*)d_in[2];
    const float* Wk  = (const float*)d_in[3];
    const float* bk  = (const float*)d_in[4];
    const float* Wv  = (const float*)d_in[5];
    const float* bv  = (const float*)d_in[6];
    const float* lng = (const float*)d_in[7];
    const float* lnb = (const float*)d_in[8];
    float* out = (float*)d_out;

    // 0) convert x, Wq, Wk, Wv to bf16 hi/lo planes
    preconv<<<dim3(576, 4), 256>>>(x, Wq, Wk, Wv);

    // 1) fused QKV projection on tensor cores: grid (12, 24) = 288 CTAs, 2/SM
    cudaFuncSetAttribute(qkv_mma, cudaFuncAttributeMaxDynamicSharedMemorySize, QKV_SMEM);
    qkv_mma<<<dim3(12, 24), 256, QKV_SMEM>>>(bq, bk, bv);

    // 2) attention: grid (6, 12, 2) = 144 CTAs (ITILE=64)
    cudaFuncSetAttribute(attn_kernel, cudaFuncAttributeMaxDynamicSharedMemorySize, ATTN_SMEM);
    attn_kernel<<<dim3(6, NHEADS, BB), 512, ATTN_SMEM>>>();

    // 3) residual + LayerNorm
    ln_kernel<<<BS, 256>>>(x, lng, lnb, out);
}

// round 17
// speedup vs baseline: 1.1063x; 1.0400x over previous
#include <cuda_runtime.h>
#include <cuda_bf16.h>
#include <cstdint>

#define H 768
#define SQ 384
#define BB 2
#define NHEADS 12
#define DHEAD 64
#define BS (BB*SQ)   // 768 rows total

// Scratch (allocation-free rule: __device__ globals)
__device__ float g_q[BS*H];
__device__ float g_k[BS*H];
__device__ float g_v[BS*H];
__device__ float g_ctx[BS*H];
// bf16 hi/lo planes (filled by preconv each call)
__device__ __nv_bfloat16 g_xh[BS*H];
__device__ __nv_bfloat16 g_xl[BS*H];
__device__ __nv_bfloat16 g_wh[3*H*H];
__device__ __nv_bfloat16 g_wl[3*H*H];

__device__ __forceinline__ float frcp_approx(float x){ float r; asm("rcp.approx.ftz.f32 %0, %1;" : "=f"(r) : "f"(x)); return r; }
__device__ __forceinline__ float fsqrt_approx(float x){ float r; asm("sqrt.approx.f32 %0, %1;" : "=f"(r) : "f"(x)); return r; }
__device__ __forceinline__ float frsqrt_approx(float x){ float r; asm("rsqrt.approx.f32 %0, %1;" : "=f"(r) : "f"(x)); return r; }

// ---- packed fp32x2 ops ----
union F2U { float2 f; unsigned long long u; };
__device__ __forceinline__ float2 f2fma(float2 a, float2 b, float2 c){
    F2U A, Bv, C, R; A.f = a; Bv.f = b; C.f = c;
    asm("fma.rn.f32x2 %0, %1, %2, %3;" : "=l"(R.u) : "l"(A.u), "l"(Bv.u), "l"(C.u));
    return R.f;
}
__device__ __forceinline__ float2 f2add(float2 a, float2 b){
    F2U A, Bv, R; A.f = a; Bv.f = b;
    asm("add.rn.f32x2 %0, %1, %2;" : "=l"(R.u) : "l"(A.u), "l"(Bv.u));
    return R.f;
}
__device__ __forceinline__ float2 f2mul(float2 a, float2 b){
    F2U A, Bv, R; A.f = a; Bv.f = b;
    asm("mul.rn.f32x2 %0, %1, %2;" : "=l"(R.u) : "l"(A.u), "l"(Bv.u));
    return R.f;
}

// ---- warp-level bf16 MMA + ldmatrix + cp.async ----
__device__ __forceinline__ void mma16816(float* d,
    uint32_t a0, uint32_t a1, uint32_t a2, uint32_t a3,
    uint32_t b0, uint32_t b1)
{
    asm("mma.sync.aligned.m16n8k16.row.col.f32.bf16.bf16.f32 "
        "{%0,%1,%2,%3}, {%4,%5,%6,%7}, {%8,%9}, {%0,%1,%2,%3};"
        : "+f"(d[0]), "+f"(d[1]), "+f"(d[2]), "+f"(d[3])
        : "r"(a0), "r"(a1), "r"(a2), "r"(a3), "r"(b0), "r"(b1));
}
__device__ __forceinline__ void ldmx4(uint32_t* r, uint32_t addr){
    asm volatile("ldmatrix.sync.aligned.m8n8.x4.shared.b16 {%0,%1,%2,%3}, [%4];"
        : "=r"(r[0]), "=r"(r[1]), "=r"(r[2]), "=r"(r[3]) : "r"(addr));
}
__device__ __forceinline__ void ldmx2(uint32_t* r, uint32_t addr){
    asm volatile("ldmatrix.sync.aligned.m8n8.x2.shared.b16 {%0,%1}, [%2];"
        : "=r"(r[0]), "=r"(r[1]) : "r"(addr));
}
__device__ __forceinline__ uint32_t smem_u32(const void* p){
    uint32_t a;
    asm("{ .reg .u64 t; cvta.to.shared.u64 t, %1; cvt.u32.u64 %0, t; }" : "=r"(a) : "l"(p));
    return a;
}
__device__ __forceinline__ void cp16(uint32_t sm, const void* gm){
    asm volatile("cp.async.cg.shared.global [%0], [%1], 16;" :: "r"(sm), "l"(gm));
}
__device__ __forceinline__ void cp_commit(){ asm volatile("cp.async.commit_group;"); }
template<int N> __device__ __forceinline__ void cp_wait(){ asm volatile("cp.async.wait_group %0;" :: "n"(N)); }

// split fp32 -> (hi, lo) bf16 pair, packed as bf16x2 words
__device__ __forceinline__ void split2(float f0, float f1, uint32_t& hw, uint32_t& lw){
    __nv_bfloat16 h0 = __float2bfloat16_rn(f0);
    __nv_bfloat16 h1 = __float2bfloat16_rn(f1);
    __nv_bfloat16 l0 = __float2bfloat16_rn(f0 - __bfloat162float(h0));
    __nv_bfloat16 l1 = __float2bfloat16_rn(f1 - __bfloat162float(h1));
    hw = (uint32_t)*(uint16_t*)&h0 | ((uint32_t)*(uint16_t*)&h1 << 16);
    lw = (uint32_t)*(uint16_t*)&l0 | ((uint32_t)*(uint16_t*)&l1 << 16);
}

// ---------------------------------------------------------------------------
// Kernel 0: convert x / Wq / Wk / Wv to bf16 hi/lo planes.
// ---------------------------------------------------------------------------
__global__ __launch_bounds__(256) void preconv(
    const float* __restrict__ x, const float* __restrict__ wq,
    const float* __restrict__ wk, const float* __restrict__ wv)
{
    const int t = blockIdx.y;
    const float* src = (t == 0) ? x : (t == 1) ? wq : (t == 2) ? wk : wv;
    __nv_bfloat16* dh = (t == 0) ? g_xh : g_wh + (size_t)(t-1)*H*H;
    __nv_bfloat16* dl = (t == 0) ? g_xl : g_wl + (size_t)(t-1)*H*H;

    const int idx = (blockIdx.x * 256 + threadIdx.x) * 4;
    float4 v = *(const float4*)&src[idx];
    uint32_t h0, l0, h1, l1;
    split2(v.x, v.y, h0, l0);
    split2(v.z, v.w, h1, l1);
    *(uint2*)((char*)dh + (size_t)idx*2) = make_uint2(h0, h1);
    *(uint2*)((char*)dl + (size_t)idx*2) = make_uint2(l0, l1);
}

// ---------------------------------------------------------------------------
// Kernel 1: fused QKV projection on tensor cores (unchanged).
// ---------------------------------------------------------------------------
#define A_BYTES (64*80)
#define B_BYTES (96*80)
#define BUF_BYTES (2*A_BYTES + 2*B_BYTES)   // 25600
#define QKV_SMEM (3*BUF_BYTES)              // 76800 -> 2 CTAs/SM

__global__ __launch_bounds__(256, 2) void qkv_mma(
    const float* __restrict__ bq, const float* __restrict__ bk,
    const float* __restrict__ bv)
{
    extern __shared__ __nv_bfloat16 smb[];
    const uint32_t sb = smem_u32(smb);

    const int tid = threadIdx.x;
    const int wid = tid >> 5, lane = tid & 31;
    const int warp_m = wid >> 2, warp_n = wid & 3;

    const int m0 = blockIdx.x * 64;
    const int ntile = blockIdx.y;
    const int z = ntile >> 3;
    const int n0 = (ntile & 7) * 96;

    const float* bias = (z == 0) ? bq : (z == 1) ? bk : bv;
    float* out = (z == 0) ? g_q : (z == 1) ? g_k : g_v;

    float acc[2][3][4];
    #pragma unroll
    for (int mi = 0; mi < 2; mi++)
        #pragma unroll
        for (int j = 0; j < 3; j++)
            #pragma unroll
            for (int e = 0; e < 4; e++) acc[mi][j][e] = 0.f;

    const int lrow = lane & 15;
    const int lkb  = (lane >> 4) * 16;
    const uint32_t aAddrH = sb + (uint32_t)((warp_m*32 + lrow) * 80 + lkb);
    const uint32_t aAddrL = aAddrH + A_BYTES;
    const int jrow  = warp_n*24 + ((lane >> 4) << 3) + (lane & 7);
    const int jkb   = ((lane >> 3) & 1) * 16;
    const uint32_t b4AddrH = sb + 2*A_BYTES + (uint32_t)(jrow * 80 + jkb);
    const uint32_t b4AddrL = b4AddrH + B_BYTES;
    const int jrow2 = warp_n*24 + 16 + (lane & 7);
    const uint32_t b2AddrH = sb + 2*A_BYTES + (uint32_t)(jrow2 * 80 + jkb);
    const uint32_t b2AddrL = b2AddrH + B_BYTES;

    uint32_t smof[5];
    const __nv_bfloat16* gm[5];
    #pragma unroll
    for (int it = 0; it < 5; it++) {
        int sidx = tid + it * 256;
        if (sidx < 512) {
            int a = sidx & 255, r = a >> 2, q = a & 3;
            smof[it] = ((sidx >= 256) ? A_BYTES : 0) + r*80 + q*16;
            gm[it] = ((sidx >= 256) ? g_xl : g_xh) + (size_t)(m0 + r)*H + q*8;
        } else {
            int t2 = sidx - 512;
            int lo = (t2 >= 384);
            int b2 = lo ? t2 - 384 : t2;
            int r = b2 >> 2, q = b2 & 3;
            smof[it] = 2*A_BYTES + (lo ? B_BYTES : 0) + r*80 + q*16;
            gm[it] = (lo ? g_wl : g_wh) + (size_t)z*H*H + (size_t)(n0 + r)*H + q*8;
        }
    }

    #pragma unroll
    for (int it = 0; it < 5; it++) cp16(sb + smof[it], gm[it]);
    cp_commit();
    #pragma unroll
    for (int it = 0; it < 5; it++) cp16(sb + BUF_BYTES + smof[it], (const char*)gm[it] + 64);
    cp_commit();

    uint32_t bufB = 0;
    for (int s = 0; s < 24; s++) {
        if (s < 23) cp_wait<1>(); else cp_wait<0>();
        __syncthreads();

        if (s < 22) {
            uint32_t nb = bufB + 2*BUF_BYTES;
            if (nb >= 3*BUF_BYTES) nb -= 3*BUF_BYTES;
            const int koff = (s + 2) * 64;
            #pragma unroll
            for (int it = 0; it < 5; it++) cp16(sb + nb + smof[it], (const char*)gm[it] + koff);
            cp_commit();
        }

        #pragma unroll
        for (int ks = 0; ks < 2; ks++) {
            const uint32_t kb = bufB + ks * 32;
            uint32_t Ah[2][4], Al[2][4], B4h[4], B4l[4], B2h[2], B2l[2];
            ldmx4(Ah[0], aAddrH + kb);
            ldmx4(Ah[1], aAddrH + kb + 16*80);
            ldmx4(Al[0], aAddrL + kb);
            ldmx4(Al[1], aAddrL + kb + 16*80);
            ldmx4(B4h, b4AddrH + kb);
            ldmx4(B4l, b4AddrL + kb);
            ldmx2(B2h, b2AddrH + kb);
            ldmx2(B2l, b2AddrL + kb);
            #pragma unroll
            for (int mi = 0; mi < 2; mi++) {
                mma16816(acc[mi][0], Ah[mi][0],Ah[mi][1],Ah[mi][2],Ah[mi][3], B4h[0],B4h[1]);
                mma16816(acc[mi][0], Ah[mi][0],Ah[mi][1],Ah[mi][2],Ah[mi][3], B4l[0],B4l[1]);
                mma16816(acc[mi][0], Al[mi][0],Al[mi][1],Al[mi][2],Al[mi][3], B4h[0],B4h[1]);
                mma16816(acc[mi][1], Ah[mi][0],Ah[mi][1],Ah[mi][2],Ah[mi][3], B4h[2],B4h[3]);
                mma16816(acc[mi][1], Ah[mi][0],Ah[mi][1],Ah[mi][2],Ah[mi][3], B4l[2],B4l[3]);
                mma16816(acc[mi][1], Al[mi][0],Al[mi][1],Al[mi][2],Al[mi][3], B4h[2],B4h[3]);
                mma16816(acc[mi][2], Ah[mi][0],Ah[mi][1],Ah[mi][2],Ah[mi][3], B2h[0],B2h[1]);
                mma16816(acc[mi][2], Ah[mi][0],Ah[mi][1],Ah[mi][2],Ah[mi][3], B2l[0],B2l[1]);
                mma16816(acc[mi][2], Al[mi][0],Al[mi][1],Al[mi][2],Al[mi][3], B2h[0],B2h[1]);
            }
        }
        bufB += BUF_BYTES;
        if (bufB >= 3*BUF_BYTES) bufB = 0;
    }

    const int gid = lane >> 2, tg = lane & 3;
    #pragma unroll
    for (int mi = 0; mi < 2; mi++) {
        int r0 = m0 + warp_m * 32 + mi * 16 + gid;
        #pragma unroll
        for (int j = 0; j < 3; j++) {
            int nc = n0 + warp_n * 24 + j * 8 + tg * 2;
            float b0 = bias[nc], b1 = bias[nc + 1];
            *(float2*)&out[(size_t)r0 * H + nc]       = make_float2(acc[mi][j][0] + b0, acc[mi][j][1] + b1);
            *(float2*)&out[(size_t)(r0 + 8) * H + nc] = make_float2(acc[mi][j][2] + b0, acc[mi][j][3] + b1);
        }
    }
}

// ---------------------------------------------------------------------------
// Kernel 2: attention. Phase 1 + softmax unchanged (fp32, f32x2, 4-way rcp
// pairing). Probs normalized + split to bf16 hi/lo overlaid into sc;
// V converted to bf16 hi/lo transposed [d][j]; phase 3 P@V on HMMA.
// ---------------------------------------------------------------------------
#define QSTR 68
#define KSTR 68
#define SCW 388              // words per sc row (1552 B)
#define VSTR 144             // V_t row stride bytes
#define QS_B 0
#define KV_B 17408
#define SC_B (17408+36864)   // 54272
#define RS_B (SC_B + 64*1552)   // 153600
#define ATTN_SMEM (RS_B + 256)  // 153856

__global__ __launch_bounds__(512) void attn_kernel()
{
    extern __shared__ float sm[];
    char* smc = (char*)sm;
    float* qs = sm;                          // [64][QSTR] fp32
    float* sc = (float*)(smc + SC_B);        // [64][SCW] fp32 scores -> P overlay
    float* rowsum = (float*)(smc + RS_B);

    const int tid = threadIdx.x;
    const int b = blockIdx.z, h = blockIdx.y;
    const int i0 = blockIdx.x * 64;
    const int wid = tid >> 5, lane = tid & 31;

    const float* Qb = g_q + (size_t)(b*SQ)*H + h*DHEAD;
    const float* Kb = g_k + (size_t)(b*SQ)*H + h*DHEAD;
    const float* Vb = g_v + (size_t)(b*SQ)*H + h*DHEAD;

    // Q tile [64][64], scaled by 4
    for (int idx = tid; idx < 64*16; idx += 512) {
        int i = idx >> 4, c4 = (idx & 15) << 2;
        float4 v = *(const float4*)&Qb[(size_t)(i0+i)*H + c4];
        v.x *= 4.f; v.y *= 4.f; v.z *= 4.f; v.w *= 4.f;
        *(float4*)&qs[i*QSTR + c4] = v;
    }

    const int tx = tid & 31;
    const int ty = tid >> 5;
    const int kr0 = tid >> 4, kc0 = (tid & 15) << 2;
    const int kr1 = kr0 + 32;

    // ---- Phase 1: scores (fp32 into sc), double-buffered K tiles ----
    float4 pk0 = *(const float4*)&Kb[(size_t)(kr0)*H + kc0];
    float4 pk1 = *(const float4*)&Kb[(size_t)(kr1)*H + kc0];

    for (int jt = 0; jt < 6; jt++) {
        int j0 = jt * 64;
        float* kb = (float*)(smc + KV_B + (jt & 1) * 17408);
        kb[(kc0+0)*KSTR + kr0] = -4.f*pk0.x;
        kb[(kc0+1)*KSTR + kr0] = -4.f*pk0.y;
        kb[(kc0+2)*KSTR + kr0] = -4.f*pk0.z;
        kb[(kc0+3)*KSTR + kr0] = -4.f*pk0.w;
        kb[(kc0+0)*KSTR + kr1] = -4.f*pk1.x;
        kb[(kc0+1)*KSTR + kr1] = -4.f*pk1.y;
        kb[(kc0+2)*KSTR + kr1] = -4.f*pk1.z;
        kb[(kc0+3)*KSTR + kr1] = -4.f*pk1.w;
        __syncthreads();
        if (jt < 5) {
            pk0 = *(const float4*)&Kb[(size_t)(j0 + 64 + kr0)*H + kc0];
            pk1 = *(const float4*)&Kb[(size_t)(j0 + 64 + kr1)*H + kc0];
        }

        float2 acc[4];
        #pragma unroll
        for (int i = 0; i < 4; i++) acc[i] = make_float2(0.f, 0.f);

        #pragma unroll 4
        for (int d = 0; d < 64; d += 4) {
            float2 nk0 = *(const float2*)&kb[(d+0)*KSTR + tx*2];
            float2 nk1 = *(const float2*)&kb[(d+1)*KSTR + tx*2];
            float2 nk2 = *(const float2*)&kb[(d+2)*KSTR + tx*2];
            float2 nk3 = *(const float2*)&kb[(d+3)*KSTR + tx*2];
            #pragma unroll
            for (int i = 0; i < 4; i++) {
                float4 q = *(const float4*)&qs[(ty*4+i)*QSTR + d];
                float2 d0 = f2add(make_float2(q.x, q.x), nk0);
                float2 d1 = f2add(make_float2(q.y, q.y), nk1);
                float2 d2 = f2add(make_float2(q.z, q.z), nk2);
                float2 d3 = f2add(make_float2(q.w, q.w), nk3);
                float2 a  = f2mul(d0, d0);
                float2 bq2 = f2mul(d1, d1);
                float2 c  = f2mul(d2, d2);
                float2 e  = f2mul(d3, d3);
                float2 ab = f2mul(a, bq2);
                float2 ce = f2mul(c, e);
                float2 sab = f2add(a, bq2);
                float2 sce = f2add(c, e);
                float2 num = f2fma(sab, ce, f2mul(sce, ab));
                float2 den = f2mul(ab, ce);
                float2 r   = make_float2(frcp_approx(den.x), frcp_approx(den.y));
                acc[i] = f2fma(num, r, acc[i]);
            }
        }
        #pragma unroll
        for (int i = 0; i < 4; i++) {
            float* row = &sc[(ty*4+i)*SCW + j0 + tx*2];
            row[0] = -0.5f * frsqrt_approx(fsqrt_approx(acc[i].x));
            row[1] = -0.5f * frsqrt_approx(fsqrt_approx(acc[i].y));
        }
    }
    __syncthreads();

    // prefetch V tile 0 (LDG latency hidden under softmax)
    float4 pv0 = *(const float4*)&Vb[(size_t)(kr0)*H + kc0];
    float4 pv1 = *(const float4*)&Vb[(size_t)(kr1)*H + kc0];

    // ---- Phase 2: softmax rows (unnormalized probs back into sc + rowsum) ----
    {
        for (int i = wid; i < 64; i += 16) {
            float m = -3.402823466e38f;
            for (int j = lane; j < SQ; j += 32) m = fmaxf(m, sc[i*SCW + j]);
            #pragma unroll
            for (int o = 16; o; o >>= 1) m = fmaxf(m, __shfl_xor_sync(0xffffffffu, m, o));
            float s = 0.f;
            for (int j = lane; j < SQ; j += 32) {
                float p = __expf(sc[i*SCW + j] - m);
                sc[i*SCW + j] = p;
                s += p;
            }
            #pragma unroll
            for (int o = 16; o; o >>= 1) s += __shfl_xor_sync(0xffffffffu, s, o);
            if (lane == 0) rowsum[i] = s;
        }
    }
    __syncthreads();

    // ---- Convert pass: P_norm -> bf16 hi/lo overlay in sc rows ----
    #pragma unroll
    for (int i = 0; i < 4; i++) {
        const int row = ty*4 + i;
        const float rs = frcp_approx(rowsum[row]);
        float2 v[6];
        #pragma unroll
        for (int t = 0; t < 6; t++)
            v[t] = *(const float2*)&sc[row*SCW + t*64 + tx*2];
        __syncwarp();
        #pragma unroll
        for (int t = 0; t < 6; t++) {
            uint32_t hw, lw;
            split2(v[t].x * rs, v[t].y * rs, hw, lw);
            *(uint32_t*)(smc + SC_B + row*1552 + t*128 + tx*4) = hw;
            *(uint32_t*)(smc + SC_B + row*1552 + 768 + t*128 + tx*4) = lw;
        }
    }

    // ---- STS V tile 0 (bf16 hi/lo, transposed [d][j]) into KV buf 0 ----
    {
        char* vb = smc + KV_B;
        float f0[4] = {pv0.x, pv0.y, pv0.z, pv0.w};
        float f1[4] = {pv1.x, pv1.y, pv1.z, pv1.w};
        #pragma unroll
        for (int e = 0; e < 4; e++) {
            __nv_bfloat16 hv = __float2bfloat16_rn(f0[e]);
            __nv_bfloat16 lv = __float2bfloat16_rn(f0[e] - __bfloat162float(hv));
            *(uint16_t*)(vb + (kc0+e)*VSTR + kr0*2)        = *(uint16_t*)&hv;
            *(uint16_t*)(vb + 9216 + (kc0+e)*VSTR + kr0*2) = *(uint16_t*)&lv;
            hv = __float2bfloat16_rn(f1[e]);
            lv = __float2bfloat16_rn(f1[e] - __bfloat162float(hv));
            *(uint16_t*)(vb + (kc0+e)*VSTR + kr1*2)        = *(uint16_t*)&hv;
            *(uint16_t*)(vb + 9216 + (kc0+e)*VSTR + kr1*2) = *(uint16_t*)&lv;
        }
    }
    __syncthreads();   // P overlay + V0 visible

    // ---- Phase 3: ctx = P @ V on tensor cores ----
    const uint32_t sbase = smem_u32(smc);
    const int wm = wid >> 2, wn = wid & 3;
    const uint32_t paH = sbase + SC_B + (uint32_t)((wm*16 + (lane & 15)) * 1552 + (lane >> 4) * 16);
    const uint32_t paL = paH + 768;
    const int vrow = wn*16 + ((lane >> 4) << 3) + (lane & 7);
    const int vkb  = ((lane >> 3) & 1) * 16;

    float acc3[2][4];
    #pragma unroll
    for (int nj = 0; nj < 2; nj++)
        #pragma unroll
        for (int e = 0; e < 4; e++) acc3[nj][e] = 0.f;

    for (int jt = 0; jt < 6; jt++) {
        if (jt > 0) {
            char* vb = smc + KV_B + (jt & 1) * 18432;
            float f0[4] = {pv0.x, pv0.y, pv0.z, pv0.w};
            float f1[4] = {pv1.x, pv1.y, pv1.z, pv1.w};
            #pragma unroll
            for (int e = 0; e < 4; e++) {
                __nv_bfloat16 hv = __float2bfloat16_rn(f0[e]);
                __nv_bfloat16 lv = __float2bfloat16_rn(f0[e] - __bfloat162float(hv));
                *(uint16_t*)(vb + (kc0+e)*VSTR + kr0*2)        = *(uint16_t*)&hv;
                *(uint16_t*)(vb + 9216 + (kc0+e)*VSTR + kr0*2) = *(uint16_t*)&lv;
                hv = __float2bfloat16_rn(f1[e]);
                lv = __float2bfloat16_rn(f1[e] - __bfloat162float(hv));
                *(uint16_t*)(vb + (kc0+e)*VSTR + kr1*2)        = *(uint16_t*)&hv;
                *(uint16_t*)(vb + 9216 + (kc0+e)*VSTR + kr1*2) = *(uint16_t*)&lv;
            }
            __syncthreads();
        }
        if (jt < 5) {
            pv0 = *(const float4*)&Vb[(size_t)((jt+1)*64 + kr0)*H + kc0];
            pv1 = *(const float4*)&Vb[(size_t)((jt+1)*64 + kr1)*H + kc0];
        }
        const uint32_t vB = sbase + KV_B + (uint32_t)((jt & 1) * 18432 + vrow*VSTR + vkb);
        #pragma unroll
        for (int ks = 0; ks < 4; ks++) {
            uint32_t Ah[4], Al[4], Bh[4], Bl[4];
            ldmx4(Ah, paH + jt*128 + ks*32);
            ldmx4(Al, paL + jt*128 + ks*32);
            ldmx4(Bh, vB + ks*32);
            ldmx4(Bl, vB + 9216 + ks*32);
            mma16816(acc3[0], Ah[0],Ah[1],Ah[2],Ah[3], Bh[0],Bh[1]);
            mma16816(acc3[0], Ah[0],Ah[1],Ah[2],Ah[3], Bl[0],Bl[1]);
            mma16816(acc3[0], Al[0],Al[1],Al[2],Al[3], Bh[0],Bh[1]);
            mma16816(acc3[1], Ah[0],Ah[1],Ah[2],Ah[3], Bh[2],Bh[3]);
            mma16816(acc3[1], Ah[0],Ah[1],Ah[2],Ah[3], Bl[2],Bl[3]);
            mma16816(acc3[1], Al[0],Al[1],Al[2],Al[3], Bh[2],Bh[3]);
        }
    }

    // ---- epilogue (P pre-normalized: direct store) ----
    const int gid = lane >> 2, tg = lane & 3;
    #pragma unroll
    for (int nj = 0; nj < 2; nj++) {
        int d0 = wn*16 + nj*8 + tg*2;
        int r0 = i0 + wm*16 + gid;
        *(float2*)&g_ctx[(size_t)(b*SQ + r0)*H + h*DHEAD + d0]     = make_float2(acc3[nj][0], acc3[nj][1]);
        *(float2*)&g_ctx[(size_t)(b*SQ + r0 + 8)*H + h*DHEAD + d0] = make_float2(acc3[nj][2], acc3[nj][3]);
    }
}

// ---------------------------------------------------------------------------
// Kernel 3: residual + LayerNorm.
// ---------------------------------------------------------------------------
__global__ __launch_bounds__(256) void ln_kernel(
    const float* __restrict__ x, const float* __restrict__ gam,
    const float* __restrict__ bet, float* __restrict__ out)
{
    const int r = blockIdx.x;
    const float* xr = x + (size_t)r * H;
    const float* cr = g_ctx + (size_t)r * H;
    const int tid = threadIdx.x;

    __shared__ float redS[8], redQ[8];

    float y[3];
    float s = 0.f, ss = 0.f;
    #pragma unroll
    for (int k = 0; k < 3; k++) {
        int j = tid + k * 256;
        y[k] = xr[j] + cr[j];
        s += y[k];
        ss += y[k] * y[k];
    }
    #pragma unroll
    for (int o = 16; o; o >>= 1) {
        s  += __shfl_xor_sync(0xffffffffu, s, o);
        ss += __shfl_xor_sync(0xffffffffu, ss, o);
    }
    const int wid = tid >> 5, lane = tid & 31;
    if (lane == 0) { redS[wid] = s; redQ[wid] = ss; }
    __syncthreads();
    if (tid == 0) {
        float a = 0.f, b2 = 0.f;
        #pragma unroll
        for (int w = 0; w < 8; w++) { a += redS[w]; b2 += redQ[w]; }
        redS[0] = a; redQ[0] = b2;
    }
    __syncthreads();
    const float mu  = redS[0] * (1.f / (float)H);
    const float var = redQ[0] * (1.f / (float)H) - mu * mu;
    const float inv = rsqrtf(var + 1e-12f);

    #pragma unroll
    for (int k = 0; k < 3; k++) {
        int j = tid + k * 256;
        out[(size_t)r * H + j] = (y[k] - mu) * inv * gam[j] + bet[j];
    }
}

// ---------------------------------------------------------------------------
extern "C" void kernel_launch(void* const* d_in, const int* in_sizes, int n_in,
                              void* d_out, int out_size)
{
    const float* x   = (const float*)d_in[0];
    const float* Wq  = (const float*)d_in[1];
    const float* bq  = (const float*)d_in[2];
    const float* Wk  = (const float*)d_in[3];
    const float* bk  = (const float*)d_in[4];
    const float* Wv  = (const float*)d_in[5];
    const float* bv  = (const float*)d_in[6];
    const float* lng = (const float*)d_in[7];
    const float* lnb = (const float*)d_in[8];
    float* out = (float*)d_out;

    // 0) convert x, Wq, Wk, Wv to bf16 hi/lo planes
    preconv<<<dim3(576, 4), 256>>>(x, Wq, Wk, Wv);

    // 1) fused QKV projection on tensor cores: grid (12, 24) = 288 CTAs, 2/SM
    cudaFuncSetAttribute(qkv_mma, cudaFuncAttributeMaxDynamicSharedMemorySize, QKV_SMEM);
    qkv_mma<<<dim3(12, 24), 256, QKV_SMEM>>>(bq, bk, bv);

    // 2) attention: grid (6, 12, 2) = 144 CTAs
    cudaFuncSetAttribute(attn_kernel, cudaFuncAttributeMaxDynamicSharedMemorySize, ATTN_SMEM);
    attn_kernel<<<dim3(6, NHEADS, BB), 512, ATTN_SMEM>>>();

    // 3) residual + LayerNorm
    ln_kernel<<<BS, 256>>>(x, lng, lnb, out);
}